// round 14
// baseline (speedup 1.0000x reference)
#include <cuda_runtime.h>
#include <cuda_bf16.h>

// Problem constants from the reference (MAP = H = W = 64).
#define HH 64
#define WW 64
#define HWSZ 4096
#define MAPC 64
#define NSPLIT 4

// Extract component i (0..7) of two float4s via predicated selects (i is
// warp-uniform -> pure SELs, no divergence, no memory).
__device__ __forceinline__ float comp4(float4 v, int i) {
    float ab = (i & 1) ? v.y : v.x;
    float cd = (i & 1) ? v.w : v.z;
    return (i & 2) ? cd : ab;
}
__device__ __forceinline__ float comp8(float4 a, float4 b, int i) {
    return (i & 4) ? comp4(b, i) : comp4(a, i);
}

// R13 skeleton (role-split 256-thread blocks, sync-free 16-pred matching)
// + R5's winning trick re-applied: the SECOND float4 of each window row is
// loaded only under a uniform predicate (needed columns spill past index 3).
// Saves ~1 L2 sector x 5 rows per (gt,channel) in the warm replay phase,
// which the harness-dur history (R5 best=8.70 with conditional loads,
// R7=8.96 unconditional) indicates is the binding resource.
__global__ void __launch_bounds__(256)
rp_kernel(const float* __restrict__ params,
          const float* __restrict__ offsets,
          const int*   __restrict__ vgt_bid,
          const int*   __restrict__ vgt_cen,
          const int*   __restrict__ pred_bid,
          const int*   __restrict__ pred_cyx,
          float* __restrict__ out,
          int n_gt, int n_pred, int C, int PP)
{
    const int gt    = blockIdx.x;
    const int chunk = blockIdx.y;
    const int tid   = threadIdx.x;
    const int lane  = tid & 31;

    const int gb = __ldg(&vgt_bid[gt]);
    const int2 gc = ((const int2*)vgt_cen)[gt];

    // ---- Matching: warp-local scan of batch gb's pred range ----
    const int2* pc2 = (const int2*)pred_cyx;
    const int lo = gb * PP;
    unsigned best = 0xFFFFFFFFu;
    for (int jj = lane; jj < PP; jj += 32) {
        const int j = lo + jj;
        int2 p = pc2[j];
        int dy = p.x - gc.x;
        int dx = p.y - gc.y;
        // batch check kept (rejects any alien pred in the range exactly as
        // the reference's inf-masking does).
        unsigned d2 = (pred_bid[j] == gb) ? (unsigned)(dy * dy + dx * dx)
                                          : 0x00040000u;
        best = min(best, (d2 << 10) | (unsigned)j);   // d2 < 2^18, j < 1024
    }
    best = __reduce_min_sync(0xFFFFFFFFu, best);       // all lanes get argmin

    const int j  = (int)(best & 1023u);
    const int2 pj = pc2[j];                            // broadcast, L1-hot
    const int cy = min(max(pj.x, 0), MAPC - 1);
    const int cx = min(max(pj.y, 0), MAPC - 1);
    const int flat = cy * MAPC + cx;

    if (chunk == 0 && tid == 0) {
        // centers_pred appended after the (n_gt, 2C) block
        out[(size_t)n_gt * 2 * C + 2 * gt]     = (float)(flat % MAPC);
        out[(size_t)n_gt * 2 * C + 2 * gt + 1] = (float)(flat / MAPC);
    }

    const int CH   = (C + NSPLIT - 1) / NSPLIT;   // channels per chunk
    const int role = tid >> 7;                    // warp-uniform: 0=bilinear, 1=max
    const int ci   = tid & 127;
    const int c    = chunk * CH + ci;
    if (ci >= CH || c >= C) return;

    const float* bp = params + ((size_t)gb * C + c) * HWSZ;

    if (role == 1) {
        // ---------- 3x3 max: 3 LDG.128 + up to 3 predicated LDG.128 ----------
        const int mbase = min(max(cx - 2, 0), WW - 8) & ~3;
        const int k0 = max(cx - 1, 0)      - mbase;
        const int k1 = cx                  - mbase;
        const int k2 = min(cx + 1, WW - 1) - mbase;
        const int r0 = max(cy - 1, 0);
        const int r2 = min(cy + 1, HH - 1);
        const bool need2 = (k2 > 3);               // block-uniform

        const float4* qr0 = (const float4*)(bp + r0 * WW + mbase);
        const float4* qr1 = (const float4*)(bp + cy * WW + mbase);
        const float4* qr2 = (const float4*)(bp + r2 * WW + mbase);
        float4 m0a = qr0[0];
        float4 m1a = qr1[0];
        float4 m2a = qr2[0];
        float4 m0b = m0a, m1b = m1a, m2b = m2a;
        if (need2) {                               // uniform: saves 3 sectors
            m0b = qr0[1];
            m1b = qr1[1];
            m2b = qr2[1];
        }

        float mx;
        mx =            comp8(m0a, m0b, k0);
        mx = fmaxf(mx,  comp8(m0a, m0b, k1));
        mx = fmaxf(mx,  comp8(m0a, m0b, k2));
        mx = fmaxf(mx,  comp8(m1a, m1b, k0));
        mx = fmaxf(mx,  comp8(m1a, m1b, k1));
        mx = fmaxf(mx,  comp8(m1a, m1b, k2));
        mx = fmaxf(mx,  comp8(m2a, m2b, k0));
        mx = fmaxf(mx,  comp8(m2a, m2b, k1));
        mx = fmaxf(mx,  comp8(m2a, m2b, k2));

        out[(size_t)gt * 2 * C + C + c] = mx;     // params_pred_max
    } else {
        // ---------- bilinear: offsets then 2 LDG.128 + up to 2 predicated ----
        const float off_y = __ldg(&offsets[((size_t)gb * 2 + 0) * HWSZ + flat]);
        const float off_x = __ldg(&offsets[((size_t)gb * 2 + 1) * HWSZ + flat]);
        const float y = (float)cy + off_y;
        const float x = (float)cx + off_x;

        const float y0f = floorf(y), x0f = floorf(x);
        const float wy1 = y - y0f,   wx1 = x - x0f;
        const float wy0 = 1.f - wy1, wx0 = 1.f - wx1;
        const int yi0 = (int)y0f, xi0 = (int)x0f;
        const bool vx0 = (xi0     >= 0) && (xi0     <= WW - 1);
        const bool vx1 = (xi0 + 1 >= 0) && (xi0 + 1 <= WW - 1);
        const bool vy0 = (yi0     >= 0) && (yi0     <= HH - 1);
        const bool vy1 = (yi0 + 1 >= 0) && (yi0 + 1 <= HH - 1);
        const int by0 = min(max(yi0,     0), HH - 1);
        const int by1 = min(max(yi0 + 1, 0), HH - 1);
        const int bb  = min(max(xi0, 0), WW - 8) & ~3;
        const int j0  = min(max(xi0     - bb, 0), 7);
        const int j1  = min(max(xi0 + 1 - bb, 0), 7);
        // highest in-bounds column index actually read (warp-uniform)
        const int jmax = vx1 ? j1 : j0;
        const bool need2b = (jmax > 3);

        const float4* qb0 = (const float4*)(bp + by0 * WW + bb);
        const float4* qb1 = (const float4*)(bp + by1 * WW + bb);
        float4 b0a = qb0[0];
        float4 b1a = qb1[0];
        float4 b0b = b0a, b1b = b1a;
        if (need2b) {                              // uniform: saves 2 sectors
            b0b = qb0[1];
            b1b = qb1[1];
        }

        float c00 = (vy0 && vx0) ? comp8(b0a, b0b, j0) : 0.f;
        float c01 = (vy0 && vx1) ? comp8(b0a, b0b, j1) : 0.f;
        float c10 = (vy1 && vx0) ? comp8(b1a, b1b, j0) : 0.f;
        float c11 = (vy1 && vx1) ? comp8(b1a, b1b, j1) : 0.f;

        float v = wy0 * wx0 * c00 + wy0 * wx1 * c01
                + wy1 * wx0 * c10 + wy1 * wx1 * c11;

        out[(size_t)gt * 2 * C + c] = v;          // params_pred (bilinear)
    }
}

extern "C" void kernel_launch(void* const* d_in, const int* in_sizes, int n_in,
                              void* d_out, int out_size)
{
    const float* params   = (const float*)d_in[0];  // (B, C, 64, 64) f32
    const float* offsets  = (const float*)d_in[1];  // (B, 2, 64, 64) f32
    const int*   vgt_bid  = (const int*)d_in[2];    // (n_gt,)
    const int*   vgt_cen  = (const int*)d_in[3];    // (n_gt, 2)
    const int*   pred_bid = (const int*)d_in[4];    // (n_pred,)
    const int*   pred_cyx = (const int*)d_in[5];    // (n_pred, 2)
    float* out = (float*)d_out;

    const int n_gt   = in_sizes[2];
    const int n_pred = in_sizes[4];
    const int B      = in_sizes[1] / (2 * HWSZ);
    const int C      = in_sizes[0] / (B * HWSZ);
    const int PP     = n_pred / B;                  // preds per image (16)

    dim3 grid(n_gt, NSPLIT);
    rp_kernel<<<grid, 256>>>(params, offsets, vgt_bid, vgt_cen,
                             pred_bid, pred_cyx, out, n_gt, n_pred, C, PP);
}

// round 15
// speedup vs baseline: 1.0036x; 1.0036x over previous
#include <cuda_runtime.h>
#include <cuda_bf16.h>

// Problem constants from the reference (MAP = H = W = 64).
#define HH 64
#define WW 64
#define HWSZ 4096
#define MAPC 64
#define NSPLIT 4

// Extract component i (0..7) of two float4s via predicated selects (i is
// warp-uniform -> pure SELs, no divergence, no memory).
__device__ __forceinline__ float comp4(float4 v, int i) {
    float ab = (i & 1) ? v.y : v.x;
    float cd = (i & 1) ? v.w : v.z;
    return (i & 2) ? cd : ab;
}
__device__ __forceinline__ float comp8(float4 a, float4 b, int i) {
    return (i & 4) ? comp4(b, i) : comp4(a, i);
}

// R13 skeleton (role-split 256-thread blocks, sync-free 16-pred matching,
// unconditional window loads — best measured cold time). NEW: the winner's
// coordinates come from __shfl_sync instead of re-loading pc2[j], removing
// one dependent ~250-cycle warm-L2 latency from every block's critical path
// (PP<=32 so the winning lane always holds p in a register).
__global__ void __launch_bounds__(256)
rp_kernel(const float* __restrict__ params,
          const float* __restrict__ offsets,
          const int*   __restrict__ vgt_bid,
          const int*   __restrict__ vgt_cen,
          const int*   __restrict__ pred_bid,
          const int*   __restrict__ pred_cyx,
          float* __restrict__ out,
          int n_gt, int n_pred, int C, int PP)
{
    const int gt    = blockIdx.x;
    const int chunk = blockIdx.y;
    const int tid   = threadIdx.x;
    const int lane  = tid & 31;

    const int gb = __ldg(&vgt_bid[gt]);
    const int2 gc = ((const int2*)vgt_cen)[gt];

    // ---- Matching: warp-local scan of batch gb's pred range ----
    const int2* pc2 = (const int2*)pred_cyx;
    const int lo = gb * PP;
    unsigned best = 0xFFFFFFFFu;
    int2 p0 = make_int2(0, 0);                  // lane's first-iteration pred
    for (int jj = lane; jj < PP; jj += 32) {
        const int j = lo + jj;
        int2 p = pc2[j];
        if (jj == lane) p0 = p;                 // kept for the shuffle below
        int dy = p.x - gc.x;
        int dx = p.y - gc.y;
        // batch check kept (rejects any alien pred in the range exactly as
        // the reference's inf-masking does).
        unsigned d2 = (pred_bid[j] == gb) ? (unsigned)(dy * dy + dx * dx)
                                          : 0x00040000u;
        best = min(best, (d2 << 10) | (unsigned)j);   // d2 < 2^18, j < 1024
    }
    best = __reduce_min_sync(0xFFFFFFFFu, best);       // all lanes get argmin

    const int j   = (int)(best & 1023u);
    const int jjw = j - lo;                            // winner's in-range idx
    int2 pj;
    if (jjw < 32) {                                    // uniform fast path
        pj.x = __shfl_sync(0xFFFFFFFFu, p0.x, jjw);
        pj.y = __shfl_sync(0xFFFFFFFFu, p0.y, jjw);
    } else {
        pj = pc2[j];                                   // PP>32 fallback
    }
    const int cy = min(max(pj.x, 0), MAPC - 1);
    const int cx = min(max(pj.y, 0), MAPC - 1);
    const int flat = cy * MAPC + cx;

    if (chunk == 0 && tid == 0) {
        // centers_pred appended after the (n_gt, 2C) block
        out[(size_t)n_gt * 2 * C + 2 * gt]     = (float)(flat % MAPC);
        out[(size_t)n_gt * 2 * C + 2 * gt + 1] = (float)(flat / MAPC);
    }

    const int CH   = (C + NSPLIT - 1) / NSPLIT;   // channels per chunk
    const int role = tid >> 7;                    // warp-uniform: 0=bilinear, 1=max
    const int ci   = tid & 127;
    const int c    = chunk * CH + ci;
    if (ci >= CH || c >= C) return;

    const float* bp = params + ((size_t)gb * C + c) * HWSZ;

    if (role == 1) {
        // ---------- 3x3 max: 6 unconditional LDG.128, one batch ----------
        const int mbase = min(max(cx - 2, 0), WW - 8) & ~3;
        const int k0 = max(cx - 1, 0)      - mbase;
        const int k1 = cx                  - mbase;
        const int k2 = min(cx + 1, WW - 1) - mbase;
        const int r0 = max(cy - 1, 0);
        const int r2 = min(cy + 1, HH - 1);

        const float4* qr0 = (const float4*)(bp + r0 * WW + mbase);
        const float4* qr1 = (const float4*)(bp + cy * WW + mbase);
        const float4* qr2 = (const float4*)(bp + r2 * WW + mbase);
        float4 m0a = qr0[0], m0b = qr0[1];
        float4 m1a = qr1[0], m1b = qr1[1];
        float4 m2a = qr2[0], m2b = qr2[1];

        float mx;
        mx =            comp8(m0a, m0b, k0);
        mx = fmaxf(mx,  comp8(m0a, m0b, k1));
        mx = fmaxf(mx,  comp8(m0a, m0b, k2));
        mx = fmaxf(mx,  comp8(m1a, m1b, k0));
        mx = fmaxf(mx,  comp8(m1a, m1b, k1));
        mx = fmaxf(mx,  comp8(m1a, m1b, k2));
        mx = fmaxf(mx,  comp8(m2a, m2b, k0));
        mx = fmaxf(mx,  comp8(m2a, m2b, k1));
        mx = fmaxf(mx,  comp8(m2a, m2b, k2));

        out[(size_t)gt * 2 * C + C + c] = mx;     // params_pred_max
    } else {
        // ---------- bilinear: offsets (broadcast) then 4 LDG.128 ----------
        const float off_y = __ldg(&offsets[((size_t)gb * 2 + 0) * HWSZ + flat]);
        const float off_x = __ldg(&offsets[((size_t)gb * 2 + 1) * HWSZ + flat]);
        const float y = (float)cy + off_y;
        const float x = (float)cx + off_x;

        const float y0f = floorf(y), x0f = floorf(x);
        const float wy1 = y - y0f,   wx1 = x - x0f;
        const float wy0 = 1.f - wy1, wx0 = 1.f - wx1;
        const int yi0 = (int)y0f, xi0 = (int)x0f;
        const bool vx0 = (xi0     >= 0) && (xi0     <= WW - 1);
        const bool vx1 = (xi0 + 1 >= 0) && (xi0 + 1 <= WW - 1);
        const bool vy0 = (yi0     >= 0) && (yi0     <= HH - 1);
        const bool vy1 = (yi0 + 1 >= 0) && (yi0 + 1 <= HH - 1);
        const int by0 = min(max(yi0,     0), HH - 1);
        const int by1 = min(max(yi0 + 1, 0), HH - 1);
        const int bb  = min(max(xi0, 0), WW - 8) & ~3;
        const int j0  = min(max(xi0     - bb, 0), 7);
        const int j1  = min(max(xi0 + 1 - bb, 0), 7);

        const float4* qb0 = (const float4*)(bp + by0 * WW + bb);
        const float4* qb1 = (const float4*)(bp + by1 * WW + bb);
        float4 b0a = qb0[0], b0b = qb0[1];
        float4 b1a = qb1[0], b1b = qb1[1];

        float c00 = (vy0 && vx0) ? comp8(b0a, b0b, j0) : 0.f;
        float c01 = (vy0 && vx1) ? comp8(b0a, b0b, j1) : 0.f;
        float c10 = (vy1 && vx0) ? comp8(b1a, b1b, j0) : 0.f;
        float c11 = (vy1 && vx1) ? comp8(b1a, b1b, j1) : 0.f;

        float v = wy0 * wx0 * c00 + wy0 * wx1 * c01
                + wy1 * wx0 * c10 + wy1 * wx1 * c11;

        out[(size_t)gt * 2 * C + c] = v;          // params_pred (bilinear)
    }
}

extern "C" void kernel_launch(void* const* d_in, const int* in_sizes, int n_in,
                              void* d_out, int out_size)
{
    const float* params   = (const float*)d_in[0];  // (B, C, 64, 64) f32
    const float* offsets  = (const float*)d_in[1];  // (B, 2, 64, 64) f32
    const int*   vgt_bid  = (const int*)d_in[2];    // (n_gt,)
    const int*   vgt_cen  = (const int*)d_in[3];    // (n_gt, 2)
    const int*   pred_bid = (const int*)d_in[4];    // (n_pred,)
    const int*   pred_cyx = (const int*)d_in[5];    // (n_pred, 2)
    float* out = (float*)d_out;

    const int n_gt   = in_sizes[2];
    const int n_pred = in_sizes[4];
    const int B      = in_sizes[1] / (2 * HWSZ);
    const int C      = in_sizes[0] / (B * HWSZ);
    const int PP     = n_pred / B;                  // preds per image (16)

    dim3 grid(n_gt, NSPLIT);
    rp_kernel<<<grid, 256>>>(params, offsets, vgt_bid, vgt_cen,
                             pred_bid, pred_cyx, out, n_gt, n_pred, C, PP);
}